// round 15
// baseline (speedup 1.0000x reference)
#include <cuda_runtime.h>
#include <cuda_bf16.h>
#include <cstdint>

#define EPS 1e-5f

static constexpr int MAX_N = 50048;    // nodes (actual 50000)
static constexpr int MAX_E = 600064;   // edges (actual 600000)

// ---------------- scratch (device globals; no allocation allowed) ------------
__device__ float  g_deg[MAX_N];
__device__ int    g_cnt[MAX_N];
__device__ int    g_fill[MAX_N];
__device__ int    g_rowptr[MAX_N + 1];
__device__ int2   g_csr[MAX_E];        // (src, norm-bits)
__device__ float  g_dinv[MAX_N];
__device__ float  g_normself[MAX_N];
__device__ float4 g_h2[MAX_N * 32];    // GEMM output (up to 128 f/node)
__device__ float4 g_out[MAX_N * 32];   // aggregation output
__device__ float  g_stats[384];        // L1: [0:128)sum [128:256)sq ; L2: [256:320)sum [320:384)sq
__device__ unsigned long long g_scanstate[64];

// ---------------- PDL helpers --------------------------------------------------
__device__ __forceinline__ void pdl_wait() {
    asm volatile("griddepcontrol.wait;" ::: "memory");
}
__device__ __forceinline__ void pdl_trigger() {
    asm volatile("griddepcontrol.launch_dependents;" ::: "memory");
}

// ---------------- prep kernels (scalar: wavefront-bound, max occupancy) -------
__global__ void k_init(float* deg, int* cnt, float* stats, unsigned long long* state, int n) {
    int i = blockIdx.x * blockDim.x + threadIdx.x;
    if (i < n) { deg[i] = 1.0f; cnt[i] = 0; }   // self loop weight 1
    if (i < 384) stats[i] = 0.0f;               // zero ALL stats (both layers)
    if (i < 64) state[i] = 0ull;                // reset scan lookback state
}

__global__ void k_prep_edge(const int* __restrict__ dst, const float* __restrict__ w,
                            float* deg, int* cnt, int e) {
    pdl_wait();
    int i = blockIdx.x * blockDim.x + threadIdx.x;
    if (i < e) {
        int d = dst[i];
        atomicAdd(deg + d, w[i]);
        atomicAdd(cnt + d, 1);
    }
}

// ---- fused single-pass scan (decoupled lookback) + dinv/normself -------------
__global__ void k_scan(const int* __restrict__ cnt, const float* __restrict__ deg,
                       float* dinv, float* normself, int* rowptr, int* fill,
                       volatile unsigned long long* state, int n, int e) {
    pdl_wait();
    __shared__ int warpTot[8];
    __shared__ int blockOffSh;
    const int tid = threadIdx.x;
    const int lane = tid & 31;
    const int wid = tid >> 5;
    int tbase = blockIdx.x * 2048 + tid * 8;
    int v[8];
    int s = 0;
#pragma unroll
    for (int i = 0; i < 8; i++) {
        int idx = tbase + i;
        v[i] = (idx < n) ? cnt[idx] : 0;
        s += v[i];
        if (idx < n) {
            float d = deg[idx];
            float r = (d > 0.f) ? rsqrtf(d) : 0.f;
            dinv[idx] = r;
            normself[idx] = r * r;
        }
    }
    int inc = s;
#pragma unroll
    for (int o = 1; o < 32; o <<= 1) {
        int t = __shfl_up_sync(0xffffffffu, inc, o);
        if (lane >= o) inc += t;
    }
    if (lane == 31) warpTot[wid] = inc;
    __syncthreads();
    if (wid == 0) {
        int wv = (lane < 8) ? warpTot[lane] : 0;
        int winc = wv;
#pragma unroll
        for (int o = 1; o < 8; o <<= 1) {
            int t = __shfl_up_sync(0xffffffffu, winc, o);
            if (lane >= o) winc += t;
        }
        if (lane < 8) warpTot[lane] = winc - wv;   // exclusive warp offsets
        int blockTotal = __shfl_sync(0xffffffffu, winc, 7);
        if (lane == 0) {
            if (blockIdx.x == 0) {
                __threadfence();
                state[0] = ((unsigned long long)blockTotal << 2) | 2ull;  // prefix
                blockOffSh = 0;
                rowptr[n] = e;
            } else {
                __threadfence();
                state[blockIdx.x] = ((unsigned long long)blockTotal << 2) | 1ull;  // aggregate
                int excl = 0;
                int j = blockIdx.x - 1;
                while (true) {
                    unsigned long long vv;
                    do { vv = state[j]; } while ((vv & 3ull) == 0ull);
                    excl += (int)(vv >> 2);
                    if ((vv & 3ull) == 2ull) break;
                    j--;
                }
                __threadfence();
                state[blockIdx.x] = ((unsigned long long)(excl + blockTotal) << 2) | 2ull;
                blockOffSh = excl;
            }
        }
    }
    __syncthreads();
    int run = blockOffSh + warpTot[wid] + (inc - s);
#pragma unroll
    for (int i = 0; i < 8; i++) {
        int idx = tbase + i;
        if (idx < n) {
            rowptr[idx] = run;
            fill[idx] = run;
            run += v[i];
        }
    }
}

__global__ void k_place(const int* __restrict__ src, const int* __restrict__ dst,
                        const float* __restrict__ w, const float* __restrict__ dinv,
                        int* fill, int2* csr, int e) {
    pdl_wait();
    int i = blockIdx.x * blockDim.x + threadIdx.x;
    if (i < e) {
        int s = src[i], d = dst[i];
        float nm = dinv[s] * w[i] * dinv[d];
        int pos = atomicAdd(fill + d, 1);
        csr[pos] = make_int2(s, __float_as_int(nm));
    }
}

// ---------------- tf32 helpers ------------------------------------------------
__device__ __forceinline__ uint32_t f2tf32(float f) {
    uint32_t r;
    asm("cvt.rna.tf32.f32 %0, %1;" : "=r"(r) : "f"(f));
    return r;
}

__device__ __forceinline__ void mma_tf32(float c[4], uint32_t a0, uint32_t a1,
                                         uint32_t a2, uint32_t a3,
                                         uint32_t b0, uint32_t b1) {
    asm volatile(
        "mma.sync.aligned.m16n8k8.row.col.f32.tf32.tf32.f32 "
        "{%0,%1,%2,%3}, {%4,%5,%6,%7}, {%8,%9}, {%0,%1,%2,%3};"
        : "+f"(c[0]), "+f"(c[1]), "+f"(c[2]), "+f"(c[3])
        : "r"(a0), "r"(a1), "r"(a2), "r"(a3), "r"(b0), "r"(b1));
}

// ---------------- tf32 GEMM v2: BM=64, BK=64 k-tiling, 4x2 warp grid ----------
// High occupancy (52/36/28 KB smem -> 4-6 blocks/SM). Inline BN(+ReLU) on A.
template <int K, int NOUT, bool BN>
__global__ void k_gemm_tc(const float* __restrict__ A, const float* __restrict__ B,
                          float* __restrict__ C, int M,
                          const float* __restrict__ gamma, const float* __restrict__ beta,
                          const float* __restrict__ stats, float invN) {
    constexpr int BM = 64;
    constexpr int BK = 64;
    constexpr int SA = BK + 4;
    constexpr int SB = NOUT + 8;
    constexpr int NW = NOUT / 2;     // columns per warp-column group
    constexpr int NT = NW / 8;       // n8-tiles per warp (8/4/2)

    extern __shared__ uint32_t sm[];
    uint32_t* As = sm;               // [BM][SA]
    uint32_t* Bs = sm + BM * SA;     // [BK][SB]
    __shared__ float sscale[K];
    __shared__ float sshift[K];

    const int tid = threadIdx.x;
    const int lane = tid & 31;
    const int warp = tid >> 5;
    const int wr = warp & 3;         // warp row 0..3 (16 rows each)
    const int wc = warp >> 2;        // warp col 0..1 (NW cols each)
    const int rowBase = blockIdx.x * BM;

    pdl_wait();   // predecessor (agg) output visible

    if (BN && tid < K) {
        float s = stats[tid];
        float q = stats[K + tid];
        float mean = s * invN;
        float var = q * invN - mean * mean;
        float sc = gamma[tid] * rsqrtf(var + EPS);
        sscale[tid] = sc;
        sshift[tid] = beta[tid] - mean * sc;
    }
    if (BN) __syncthreads();

    float acc[NT][4];
#pragma unroll
    for (int nt = 0; nt < NT; nt++) {
        acc[nt][0] = 0.f; acc[nt][1] = 0.f; acc[nt][2] = 0.f; acc[nt][3] = 0.f;
    }

    const int r0 = wr * 16 + (lane >> 2);
    const int c0 = lane & 3;
    const int bcol = lane >> 2;

    for (int kt = 0; kt < K; kt += BK) {
        // stage A tile (BM x BK) with optional BN+ReLU
#pragma unroll
        for (int l = tid; l < BM * BK / 4; l += 256) {
            int r = l / (BK / 4);
            int c4 = l % (BK / 4);
            int gr = rowBase + r;
            float4 v = make_float4(0.f, 0.f, 0.f, 0.f);
            if (gr < M) v = *reinterpret_cast<const float4*>(A + (size_t)gr * K + kt + c4 * 4);
            if (BN) {
                int kb = kt + c4 * 4;
                v.x = fmaxf(fmaf(v.x, sscale[kb + 0], sshift[kb + 0]), 0.f);
                v.y = fmaxf(fmaf(v.y, sscale[kb + 1], sshift[kb + 1]), 0.f);
                v.z = fmaxf(fmaf(v.z, sscale[kb + 2], sshift[kb + 2]), 0.f);
                v.w = fmaxf(fmaf(v.w, sscale[kb + 3], sshift[kb + 3]), 0.f);
            }
            uint32_t* p = As + r * SA + c4 * 4;
            p[0] = f2tf32(v.x); p[1] = f2tf32(v.y); p[2] = f2tf32(v.z); p[3] = f2tf32(v.w);
        }
        // stage B tile (BK x NOUT)
#pragma unroll
        for (int l = tid; l < BK * NOUT / 4; l += 256) {
            int r = l / (NOUT / 4);
            int c4 = l % (NOUT / 4);
            float4 v = *reinterpret_cast<const float4*>(B + (size_t)(kt + r) * NOUT + c4 * 4);
            uint32_t* p = Bs + r * SB + c4 * 4;
            p[0] = f2tf32(v.x); p[1] = f2tf32(v.y); p[2] = f2tf32(v.z); p[3] = f2tf32(v.w);
        }
        __syncthreads();
#pragma unroll
        for (int kk = 0; kk < BK; kk += 8) {
            uint32_t a0 = As[r0 * SA + kk + c0];
            uint32_t a1 = As[(r0 + 8) * SA + kk + c0];
            uint32_t a2 = As[r0 * SA + kk + c0 + 4];
            uint32_t a3 = As[(r0 + 8) * SA + kk + c0 + 4];
#pragma unroll
            for (int nt = 0; nt < NT; nt++) {
                uint32_t b0 = Bs[(kk + c0) * SB + wc * NW + nt * 8 + bcol];
                uint32_t b1 = Bs[(kk + c0 + 4) * SB + wc * NW + nt * 8 + bcol];
                mma_tf32(acc[nt], a0, a1, a2, a3, b0, b1);
            }
        }
        __syncthreads();
    }
    pdl_trigger();   // all global reads of A done

    int gr0 = rowBase + r0;
    int gr1 = gr0 + 8;
    if (gr0 < M) {
#pragma unroll
        for (int nt = 0; nt < NT; nt++)
            *reinterpret_cast<float2*>(C + (size_t)gr0 * NOUT + wc * NW + nt * 8 + c0 * 2) =
                make_float2(acc[nt][0], acc[nt][1]);
    }
    if (gr1 < M) {
#pragma unroll
        for (int nt = 0; nt < NT; nt++)
            *reinterpret_cast<float2*>(C + (size_t)gr1 * NOUT + wc * NW + nt * 8 + c0 * 2) =
                make_float2(acc[nt][2], acc[nt][3]);
    }
}

// ---------------- pull aggregation (8-edge unroll, 4 accumulator sets) --------
template <int FEAT, bool STATS>
__global__ void k_agg(const int* __restrict__ rowptr, const int2* __restrict__ csr,
                      const float* __restrict__ h2, const float* __restrict__ bias,
                      const float* __restrict__ normself, float* __restrict__ out,
                      float* stats, int n) {
    constexpr int LPN = FEAT / 4;     // lanes per node
    constexpr int NPW = 32 / LPN;     // nodes per warp
    const int lane = threadIdx.x & 31;
    const int warpG = (blockIdx.x * blockDim.x + threadIdx.x) >> 5;
    const int nWarps = (gridDim.x * blockDim.x) >> 5;
    const int sub = lane / LPN;
    const int fc = lane % LPN;

    pdl_trigger();
    pdl_wait();

    float4 bb = *reinterpret_cast<const float4*>(bias + fc * 4);

    float s0 = 0.f, s1 = 0.f, s2 = 0.f, s3 = 0.f;
    float q0 = 0.f, q1 = 0.f, q2 = 0.f, q3 = 0.f;

    for (int node = warpG * NPW + sub; node < n; node += nWarps * NPW) {
        int beg = rowptr[node];
        int end = rowptr[node + 1];
        float ns = normself[node];
        float4 h = *reinterpret_cast<const float4*>(h2 + (size_t)node * FEAT + fc * 4);
        float4 aA = make_float4(fmaf(ns, h.x, bb.x), fmaf(ns, h.y, bb.y),
                                fmaf(ns, h.z, bb.z), fmaf(ns, h.w, bb.w));
        float4 aB = make_float4(0.f, 0.f, 0.f, 0.f);
        float4 aC = make_float4(0.f, 0.f, 0.f, 0.f);
        float4 aD = make_float4(0.f, 0.f, 0.f, 0.f);
        int e = beg;
        for (; e + 7 < end; e += 8) {
            int2 m0 = csr[e],     m1 = csr[e + 1], m2 = csr[e + 2], m3 = csr[e + 3];
            int2 m4 = csr[e + 4], m5 = csr[e + 5], m6 = csr[e + 6], m7 = csr[e + 7];
            float4 v0 = *reinterpret_cast<const float4*>(h2 + (size_t)m0.x * FEAT + fc * 4);
            float4 v1 = *reinterpret_cast<const float4*>(h2 + (size_t)m1.x * FEAT + fc * 4);
            float4 v2 = *reinterpret_cast<const float4*>(h2 + (size_t)m2.x * FEAT + fc * 4);
            float4 v3 = *reinterpret_cast<const float4*>(h2 + (size_t)m3.x * FEAT + fc * 4);
            float4 v4 = *reinterpret_cast<const float4*>(h2 + (size_t)m4.x * FEAT + fc * 4);
            float4 v5 = *reinterpret_cast<const float4*>(h2 + (size_t)m5.x * FEAT + fc * 4);
            float4 v6 = *reinterpret_cast<const float4*>(h2 + (size_t)m6.x * FEAT + fc * 4);
            float4 v7 = *reinterpret_cast<const float4*>(h2 + (size_t)m7.x * FEAT + fc * 4);
            float n0 = __int_as_float(m0.y), n1 = __int_as_float(m1.y);
            float n2 = __int_as_float(m2.y), n3 = __int_as_float(m3.y);
            float n4 = __int_as_float(m4.y), n5 = __int_as_float(m5.y);
            float n6 = __int_as_float(m6.y), n7 = __int_as_float(m7.y);
            aA.x = fmaf(n0, v0.x, aA.x); aB.x = fmaf(n1, v1.x, aB.x);
            aC.x = fmaf(n2, v2.x, aC.x); aD.x = fmaf(n3, v3.x, aD.x);
            aA.y = fmaf(n0, v0.y, aA.y); aB.y = fmaf(n1, v1.y, aB.y);
            aC.y = fmaf(n2, v2.y, aC.y); aD.y = fmaf(n3, v3.y, aD.y);
            aA.z = fmaf(n0, v0.z, aA.z); aB.z = fmaf(n1, v1.z, aB.z);
            aC.z = fmaf(n2, v2.z, aC.z); aD.z = fmaf(n3, v3.z, aD.z);
            aA.w = fmaf(n0, v0.w, aA.w); aB.w = fmaf(n1, v1.w, aB.w);
            aC.w = fmaf(n2, v2.w, aC.w); aD.w = fmaf(n3, v3.w, aD.w);
            aA.x = fmaf(n4, v4.x, aA.x); aB.x = fmaf(n5, v5.x, aB.x);
            aC.x = fmaf(n6, v6.x, aC.x); aD.x = fmaf(n7, v7.x, aD.x);
            aA.y = fmaf(n4, v4.y, aA.y); aB.y = fmaf(n5, v5.y, aB.y);
            aC.y = fmaf(n6, v6.y, aC.y); aD.y = fmaf(n7, v7.y, aD.y);
            aA.z = fmaf(n4, v4.z, aA.z); aB.z = fmaf(n5, v5.z, aB.z);
            aC.z = fmaf(n6, v6.z, aC.z); aD.z = fmaf(n7, v7.z, aD.z);
            aA.w = fmaf(n4, v4.w, aA.w); aB.w = fmaf(n5, v5.w, aB.w);
            aC.w = fmaf(n6, v6.w, aC.w); aD.w = fmaf(n7, v7.w, aD.w);
        }
        for (; e + 1 < end; e += 2) {
            int2 m0 = csr[e], m1 = csr[e + 1];
            float4 v0 = *reinterpret_cast<const float4*>(h2 + (size_t)m0.x * FEAT + fc * 4);
            float4 v1 = *reinterpret_cast<const float4*>(h2 + (size_t)m1.x * FEAT + fc * 4);
            float n0 = __int_as_float(m0.y), n1 = __int_as_float(m1.y);
            aA.x = fmaf(n0, v0.x, aA.x); aB.x = fmaf(n1, v1.x, aB.x);
            aA.y = fmaf(n0, v0.y, aA.y); aB.y = fmaf(n1, v1.y, aB.y);
            aA.z = fmaf(n0, v0.z, aA.z); aB.z = fmaf(n1, v1.z, aB.z);
            aA.w = fmaf(n0, v0.w, aA.w); aB.w = fmaf(n1, v1.w, aB.w);
        }
        if (e < end) {
            int2 m0 = csr[e];
            float4 v0 = *reinterpret_cast<const float4*>(h2 + (size_t)m0.x * FEAT + fc * 4);
            float n0 = __int_as_float(m0.y);
            aA.x = fmaf(n0, v0.x, aA.x);
            aA.y = fmaf(n0, v0.y, aA.y);
            aA.z = fmaf(n0, v0.z, aA.z);
            aA.w = fmaf(n0, v0.w, aA.w);
        }
        float4 acc = make_float4((aA.x + aB.x) + (aC.x + aD.x),
                                 (aA.y + aB.y) + (aC.y + aD.y),
                                 (aA.z + aB.z) + (aC.z + aD.z),
                                 (aA.w + aB.w) + (aC.w + aD.w));
        *reinterpret_cast<float4*>(out + (size_t)node * FEAT + fc * 4) = acc;
        if (STATS) {
            s0 += acc.x; s1 += acc.y; s2 += acc.z; s3 += acc.w;
            q0 = fmaf(acc.x, acc.x, q0); q1 = fmaf(acc.y, acc.y, q1);
            q2 = fmaf(acc.z, acc.z, q2); q3 = fmaf(acc.w, acc.w, q3);
        }
    }

    if (STATS) {
#pragma unroll
        for (int off = 16; off >= LPN; off >>= 1) {
            s0 += __shfl_down_sync(0xffffffffu, s0, off);
            s1 += __shfl_down_sync(0xffffffffu, s1, off);
            s2 += __shfl_down_sync(0xffffffffu, s2, off);
            s3 += __shfl_down_sync(0xffffffffu, s3, off);
            q0 += __shfl_down_sync(0xffffffffu, q0, off);
            q1 += __shfl_down_sync(0xffffffffu, q1, off);
            q2 += __shfl_down_sync(0xffffffffu, q2, off);
            q3 += __shfl_down_sync(0xffffffffu, q3, off);
        }
        __shared__ float sh_s[8][FEAT];
        __shared__ float sh_q[8][FEAT];
        const int wid = threadIdx.x >> 5;
        if (lane < LPN) {
            sh_s[wid][fc * 4 + 0] = s0; sh_s[wid][fc * 4 + 1] = s1;
            sh_s[wid][fc * 4 + 2] = s2; sh_s[wid][fc * 4 + 3] = s3;
            sh_q[wid][fc * 4 + 0] = q0; sh_q[wid][fc * 4 + 1] = q1;
            sh_q[wid][fc * 4 + 2] = q2; sh_q[wid][fc * 4 + 3] = q3;
        }
        __syncthreads();
        int tid = threadIdx.x;
        if (tid < FEAT) {
            float a = 0.f, b = 0.f;
#pragma unroll
            for (int w = 0; w < 8; w++) { a += sh_s[w][tid]; b += sh_q[w][tid]; }
            atomicAdd(&stats[tid], a);
            atomicAdd(&stats[FEAT + tid], b);
        }
    }
}

// ---------------- host orchestration -----------------------------------------
static inline int cdiv(int a, int b) { return (a + b - 1) / b; }

extern "C" void kernel_launch(void* const* d_in, const int* in_sizes, int n_in,
                              void* d_out, int out_size) {
    const float* x      = (const float*)d_in[0];
    const int*   src    = (const int*)d_in[1];
    const int*   dst    = (const int*)d_in[2];
    const float* weight = (const float*)d_in[3];
    const float* W1 = (const float*)d_in[4];
    const float* b1 = (const float*)d_in[5];
    const float* ga1 = (const float*)d_in[6];
    const float* be1 = (const float*)d_in[7];
    const float* W2 = (const float*)d_in[8];
    const float* b2 = (const float*)d_in[9];
    const float* ga2 = (const float*)d_in[10];
    const float* be2 = (const float*)d_in[11];
    const float* W3 = (const float*)d_in[12];
    const float* b3 = (const float*)d_in[13];

    const int N = in_sizes[0] / 128;
    const int E = in_sizes[1];
    float* outp = (float*)d_out;

    void *p_deg, *p_cnt, *p_fill, *p_rowptr, *p_csr, *p_dinv, *p_ns, *p_h2, *p_out;
    void *p_state, *p_stats;
    cudaGetSymbolAddress(&p_deg, g_deg);
    cudaGetSymbolAddress(&p_cnt, g_cnt);
    cudaGetSymbolAddress(&p_fill, g_fill);
    cudaGetSymbolAddress(&p_rowptr, g_rowptr);
    cudaGetSymbolAddress(&p_csr, g_csr);
    cudaGetSymbolAddress(&p_dinv, g_dinv);
    cudaGetSymbolAddress(&p_ns, g_normself);
    cudaGetSymbolAddress(&p_h2, g_h2);
    cudaGetSymbolAddress(&p_out, g_out);
    cudaGetSymbolAddress(&p_state, g_scanstate);
    cudaGetSymbolAddress(&p_stats, g_stats);
    float* deg = (float*)p_deg;
    int* cnt = (int*)p_cnt;
    int* fill = (int*)p_fill;
    int* rowptr = (int*)p_rowptr;
    int2* csr = (int2*)p_csr;
    float* dinv = (float*)p_dinv;
    float* normself = (float*)p_ns;
    float* h2 = (float*)p_h2;
    float* agg = (float*)p_out;
    unsigned long long* scanstate = (unsigned long long*)p_state;
    float* stats1 = (float*)p_stats;        // layer1: 256 floats
    float* stats2 = (float*)p_stats + 256;  // layer2: 128 floats

    const float invN = 1.0f / (float)N;

    // new smem sizes: BM=64, BK=64 tiling
    const int smem1 = (64 * 68 + 64 * (128 + 8)) * 4;   // 52224
    const int smem2 = (64 * 68 + 64 * (64 + 8)) * 4;    // 35840
    const int smem3 = (64 * 68 + 64 * (32 + 8)) * 4;    // 27648
    cudaFuncSetAttribute(k_gemm_tc<128, 128, false>,
                         cudaFuncAttributeMaxDynamicSharedMemorySize, smem1);
    cudaFuncSetAttribute(k_gemm_tc<128, 64, true>,
                         cudaFuncAttributeMaxDynamicSharedMemorySize, smem2);
    cudaFuncSetAttribute(k_gemm_tc<64, 32, true>,
                         cudaFuncAttributeMaxDynamicSharedMemorySize, smem3);

    // side stream + fork/join events (host-side objects only)
    cudaStream_t s2;
    cudaEvent_t evFork, evJoin;
    cudaStreamCreateWithFlags(&s2, cudaStreamNonBlocking);
    cudaEventCreateWithFlags(&evFork, cudaEventDisableTiming);
    cudaEventCreateWithFlags(&evJoin, cudaEventDisableTiming);

    const int scanGrid = cdiv(N, 2048);   // 25 blocks for N=50000
    const int gemmGrid = cdiv(N, 64);     // BM=64
    const int aggGrid = 1184;             // 8 blocks/SM

    // PDL launch attribute (shared)
    cudaLaunchAttribute pdlAttr[1];
    pdlAttr[0].id = cudaLaunchAttributeProgrammaticStreamSerialization;
    pdlAttr[0].val.programmaticStreamSerializationAllowed = 1;

    // ---- fork: CSR/normalization prep on s2 (PDL-chained), concurrent with GEMM1 ----
    cudaEventRecord(evFork, 0);
    cudaStreamWaitEvent(s2, evFork, 0);

    k_init<<<cdiv(N, 256), 256, 0, s2>>>(deg, cnt, stats1, scanstate, N);
    {
        cudaLaunchConfig_t cfg{};
        cfg.gridDim = dim3(cdiv(E, 256), 1, 1);
        cfg.blockDim = dim3(256, 1, 1);
        cfg.stream = s2;
        cfg.attrs = pdlAttr; cfg.numAttrs = 1;
        cudaLaunchKernelEx(&cfg, k_prep_edge, dst, weight, deg, cnt, E);
    }
    {
        cudaLaunchConfig_t cfg{};
        cfg.gridDim = dim3(scanGrid, 1, 1);
        cfg.blockDim = dim3(256, 1, 1);
        cfg.stream = s2;
        cfg.attrs = pdlAttr; cfg.numAttrs = 1;
        cudaLaunchKernelEx(&cfg, k_scan, (const int*)cnt, (const float*)deg,
                           dinv, normself, rowptr, fill,
                           (volatile unsigned long long*)scanstate, N, E);
    }
    {
        cudaLaunchConfig_t cfg{};
        cfg.gridDim = dim3(cdiv(E, 256), 1, 1);
        cfg.blockDim = dim3(256, 1, 1);
        cfg.stream = s2;
        cfg.attrs = pdlAttr; cfg.numAttrs = 1;
        cudaLaunchKernelEx(&cfg, k_place, src, dst, weight, (const float*)dinv,
                           fill, csr, E);
    }
    cudaEventRecord(evJoin, s2);

    // Layer-1 GEMM on main stream (independent of prep; starts at t=0)
    k_gemm_tc<128, 128, false><<<gemmGrid, 256, smem1>>>(x, W1, h2, N,
                                                         nullptr, nullptr, nullptr, invN);

    // ---- join: everything after needs both GEMM1 and the CSR ----
    cudaStreamWaitEvent(0, evJoin, 0);

    // agg1: plain launch (predecessor is an event-wait, not a kernel)
    k_agg<128, true><<<aggGrid, 256>>>(rowptr, csr, h2, b1, normself, agg, stats1, N);

    {
        cudaLaunchConfig_t cfg{};
        cfg.gridDim = dim3(gemmGrid, 1, 1);
        cfg.blockDim = dim3(256, 1, 1);
        cfg.dynamicSmemBytes = smem2;
        cfg.stream = 0;
        cfg.attrs = pdlAttr;
        cfg.numAttrs = 1;
        cudaLaunchKernelEx(&cfg, k_gemm_tc<128, 64, true>, (const float*)agg, W2, h2, N,
                           ga1, be1, (const float*)stats1, invN);
    }
    {
        cudaLaunchConfig_t cfg{};
        cfg.gridDim = dim3(aggGrid, 1, 1);
        cfg.blockDim = dim3(256, 1, 1);
        cfg.dynamicSmemBytes = 0;
        cfg.stream = 0;
        cfg.attrs = pdlAttr;
        cfg.numAttrs = 1;
        cudaLaunchKernelEx(&cfg, k_agg<64, true>, (const int*)rowptr, (const int2*)csr,
                           (const float*)h2, b2, (const float*)normself, agg, stats2, N);
    }
    {
        cudaLaunchConfig_t cfg{};
        cfg.gridDim = dim3(gemmGrid, 1, 1);
        cfg.blockDim = dim3(256, 1, 1);
        cfg.dynamicSmemBytes = smem3;
        cfg.stream = 0;
        cfg.attrs = pdlAttr;
        cfg.numAttrs = 1;
        cudaLaunchKernelEx(&cfg, k_gemm_tc<64, 32, true>, (const float*)agg, W3, h2, N,
                           ga2, be2, (const float*)stats2, invN);
    }
    {
        cudaLaunchConfig_t cfg{};
        cfg.gridDim = dim3(aggGrid, 1, 1);
        cfg.blockDim = dim3(256, 1, 1);
        cfg.dynamicSmemBytes = 0;
        cfg.stream = 0;
        cfg.attrs = pdlAttr;
        cfg.numAttrs = 1;
        cudaLaunchKernelEx(&cfg, k_agg<32, false>, (const int*)rowptr, (const int2*)csr,
                           (const float*)h2, b3, (const float*)normself, outp,
                           (float*)nullptr, N);
    }
}

// round 16
// speedup vs baseline: 1.3310x; 1.3310x over previous
#include <cuda_runtime.h>
#include <cuda_bf16.h>
#include <cstdint>

#define EPS 1e-5f

static constexpr int MAX_N = 50048;    // nodes (actual 50000)
static constexpr int MAX_E = 600064;   // edges (actual 600000)

// ---------------- scratch (device globals; no allocation allowed) ------------
__device__ float  g_deg[MAX_N];
__device__ int    g_cnt[MAX_N];
__device__ int    g_fill[MAX_N];
__device__ int    g_rowptr[MAX_N + 1];
__device__ int2   g_csr[MAX_E];        // (src, norm-bits)
__device__ float  g_dinv[MAX_N];
__device__ float  g_normself[MAX_N];
__device__ float4 g_h2[MAX_N * 32];    // GEMM output (up to 128 f/node)
__device__ float4 g_out[MAX_N * 32];   // aggregation output
__device__ float  g_stats[384];        // L1: [0:128)sum [128:256)sq ; L2: [256:320)sum [320:384)sq
__device__ unsigned long long g_scanstate[64];

// ---------------- PDL helpers --------------------------------------------------
__device__ __forceinline__ void pdl_wait() {
    asm volatile("griddepcontrol.wait;" ::: "memory");
}
__device__ __forceinline__ void pdl_trigger() {
    asm volatile("griddepcontrol.launch_dependents;" ::: "memory");
}

// ---------------- prep kernels (scalar: wavefront-bound, max occupancy) -------
__global__ void k_init(float* deg, int* cnt, float* stats, unsigned long long* state, int n) {
    int i = blockIdx.x * blockDim.x + threadIdx.x;
    if (i < n) { deg[i] = 1.0f; cnt[i] = 0; }   // self loop weight 1
    if (i < 384) stats[i] = 0.0f;               // zero ALL stats (both layers)
    if (i < 64) state[i] = 0ull;                // reset scan lookback state
}

__global__ void k_prep_edge(const int* __restrict__ dst, const float* __restrict__ w,
                            float* deg, int* cnt, int e) {
    pdl_wait();
    int i = blockIdx.x * blockDim.x + threadIdx.x;
    if (i < e) {
        int d = dst[i];
        atomicAdd(deg + d, w[i]);
        atomicAdd(cnt + d, 1);
    }
}

// ---- fused single-pass scan (decoupled lookback) + dinv/normself -------------
__global__ void k_scan(const int* __restrict__ cnt, const float* __restrict__ deg,
                       float* dinv, float* normself, int* rowptr, int* fill,
                       volatile unsigned long long* state, int n, int e) {
    pdl_wait();
    __shared__ int warpTot[8];
    __shared__ int blockOffSh;
    const int tid = threadIdx.x;
    const int lane = tid & 31;
    const int wid = tid >> 5;
    int tbase = blockIdx.x * 2048 + tid * 8;
    int v[8];
    int s = 0;
#pragma unroll
    for (int i = 0; i < 8; i++) {
        int idx = tbase + i;
        v[i] = (idx < n) ? cnt[idx] : 0;
        s += v[i];
        if (idx < n) {
            float d = deg[idx];
            float r = (d > 0.f) ? rsqrtf(d) : 0.f;
            dinv[idx] = r;
            normself[idx] = r * r;
        }
    }
    int inc = s;
#pragma unroll
    for (int o = 1; o < 32; o <<= 1) {
        int t = __shfl_up_sync(0xffffffffu, inc, o);
        if (lane >= o) inc += t;
    }
    if (lane == 31) warpTot[wid] = inc;
    __syncthreads();
    if (wid == 0) {
        int wv = (lane < 8) ? warpTot[lane] : 0;
        int winc = wv;
#pragma unroll
        for (int o = 1; o < 8; o <<= 1) {
            int t = __shfl_up_sync(0xffffffffu, winc, o);
            if (lane >= o) winc += t;
        }
        if (lane < 8) warpTot[lane] = winc - wv;   // exclusive warp offsets
        int blockTotal = __shfl_sync(0xffffffffu, winc, 7);
        if (lane == 0) {
            if (blockIdx.x == 0) {
                __threadfence();
                state[0] = ((unsigned long long)blockTotal << 2) | 2ull;  // prefix
                blockOffSh = 0;
                rowptr[n] = e;
            } else {
                __threadfence();
                state[blockIdx.x] = ((unsigned long long)blockTotal << 2) | 1ull;  // aggregate
                int excl = 0;
                int j = blockIdx.x - 1;
                while (true) {
                    unsigned long long vv;
                    do { vv = state[j]; } while ((vv & 3ull) == 0ull);
                    excl += (int)(vv >> 2);
                    if ((vv & 3ull) == 2ull) break;
                    j--;
                }
                __threadfence();
                state[blockIdx.x] = ((unsigned long long)(excl + blockTotal) << 2) | 2ull;
                blockOffSh = excl;
            }
        }
    }
    __syncthreads();
    int run = blockOffSh + warpTot[wid] + (inc - s);
#pragma unroll
    for (int i = 0; i < 8; i++) {
        int idx = tbase + i;
        if (idx < n) {
            rowptr[idx] = run;
            fill[idx] = run;
            run += v[i];
        }
    }
}

__global__ void k_place(const int* __restrict__ src, const int* __restrict__ dst,
                        const float* __restrict__ w, const float* __restrict__ dinv,
                        int* fill, int2* csr, int e) {
    pdl_wait();
    int i = blockIdx.x * blockDim.x + threadIdx.x;
    if (i < e) {
        int s = src[i], d = dst[i];
        float nm = dinv[s] * w[i] * dinv[d];
        int pos = atomicAdd(fill + d, 1);
        csr[pos] = make_int2(s, __float_as_int(nm));
    }
}

// ---------------- tf32 helpers ------------------------------------------------
__device__ __forceinline__ uint32_t f2tf32(float f) {
    uint32_t r;
    asm("cvt.rna.tf32.f32 %0, %1;" : "=r"(r) : "f"(f));
    return r;
}

__device__ __forceinline__ void mma_tf32(float c[4], uint32_t a0, uint32_t a1,
                                         uint32_t a2, uint32_t a3,
                                         uint32_t b0, uint32_t b1) {
    asm volatile(
        "mma.sync.aligned.m16n8k8.row.col.f32.tf32.tf32.f32 "
        "{%0,%1,%2,%3}, {%4,%5,%6,%7}, {%8,%9}, {%0,%1,%2,%3};"
        : "+f"(c[0]), "+f"(c[1]), "+f"(c[2]), "+f"(c[3])
        : "r"(a0), "r"(a1), "r"(a2), "r"(a3), "r"(b0), "r"(b1));
}

// ---------------- tf32 GEMM v3: BM=128 whole-K, 512 threads, 8x2 warp grid ----
// Pre-wait B staging (overlaps predecessor agg); 16 resident warps/SM.
template <int K, int NOUT, bool BN>
__global__ void k_gemm_tc(const float* __restrict__ A, const float* __restrict__ B,
                          float* __restrict__ C, int M,
                          const float* __restrict__ gamma, const float* __restrict__ beta,
                          const float* __restrict__ stats, float invN) {
    constexpr int BM = 128;
    constexpr int SA = K + 4;
    constexpr int SB = NOUT + 8;
    constexpr int NW = NOUT / 2;     // columns per warp-column group
    constexpr int NT = NW / 8;       // n8-tiles per warp (8/4/2)

    extern __shared__ uint32_t sm[];
    uint32_t* As = sm;               // [BM][SA]
    uint32_t* Bs = sm + BM * SA;     // [K][SB]
    __shared__ float sscale[K];
    __shared__ float sshift[K];

    const int tid = threadIdx.x;     // 512 threads
    const int lane = tid & 31;
    const int warp = tid >> 5;       // 0..15
    const int wr = warp & 7;         // warp row 0..7 (16 rows each)
    const int wc = warp >> 3;        // warp col 0..1 (NW cols each)
    const int rowBase = blockIdx.x * BM;

    // --- pre-wait prologue: stage B (weights are harness inputs) ---
    for (int l = tid; l < K * NOUT / 4; l += 512) {
        int r = l / (NOUT / 4);
        int c4 = l % (NOUT / 4);
        float4 v = *reinterpret_cast<const float4*>(B + (size_t)r * NOUT + c4 * 4);
        uint32_t* p = Bs + r * SB + c4 * 4;
        p[0] = f2tf32(v.x); p[1] = f2tf32(v.y); p[2] = f2tf32(v.z); p[3] = f2tf32(v.w);
    }

    pdl_wait();   // predecessor (agg) output now visible

    if (BN && tid < K) {
        float s = stats[tid];
        float q = stats[K + tid];
        float mean = s * invN;
        float var = q * invN - mean * mean;
        float sc = gamma[tid] * rsqrtf(var + EPS);
        sscale[tid] = sc;
        sshift[tid] = beta[tid] - mean * sc;
    }
    if (BN) __syncthreads();   // sscale/sshift visible before A staging

    for (int l = tid; l < BM * K / 4; l += 512) {
        int r = l / (K / 4);
        int c4 = l % (K / 4);
        int gr = rowBase + r;
        float4 v = make_float4(0.f, 0.f, 0.f, 0.f);
        if (gr < M) v = *reinterpret_cast<const float4*>(A + (size_t)gr * K + c4 * 4);
        if (BN) {
            v.x = fmaxf(fmaf(v.x, sscale[c4 * 4 + 0], sshift[c4 * 4 + 0]), 0.f);
            v.y = fmaxf(fmaf(v.y, sscale[c4 * 4 + 1], sshift[c4 * 4 + 1]), 0.f);
            v.z = fmaxf(fmaf(v.z, sscale[c4 * 4 + 2], sshift[c4 * 4 + 2]), 0.f);
            v.w = fmaxf(fmaf(v.w, sscale[c4 * 4 + 3], sshift[c4 * 4 + 3]), 0.f);
        }
        uint32_t* p = As + r * SA + c4 * 4;
        p[0] = f2tf32(v.x); p[1] = f2tf32(v.y); p[2] = f2tf32(v.z); p[3] = f2tf32(v.w);
    }
    __syncthreads();
    pdl_trigger();   // all global reads of A done; dependents may launch

    float acc[NT][4];
#pragma unroll
    for (int nt = 0; nt < NT; nt++) {
        acc[nt][0] = 0.f; acc[nt][1] = 0.f; acc[nt][2] = 0.f; acc[nt][3] = 0.f;
    }

    const int r0 = (wr << 4) + (lane >> 2);   // 0..127
    const int c0 = lane & 3;
    const int bcol = lane >> 2;

#pragma unroll 4
    for (int kk = 0; kk < K; kk += 8) {
        uint32_t a0 = As[r0 * SA + kk + c0];
        uint32_t a1 = As[(r0 + 8) * SA + kk + c0];
        uint32_t a2 = As[r0 * SA + kk + c0 + 4];
        uint32_t a3 = As[(r0 + 8) * SA + kk + c0 + 4];
#pragma unroll
        for (int nt = 0; nt < NT; nt++) {
            uint32_t b0 = Bs[(kk + c0) * SB + wc * NW + nt * 8 + bcol];
            uint32_t b1 = Bs[(kk + c0 + 4) * SB + wc * NW + nt * 8 + bcol];
            mma_tf32(acc[nt], a0, a1, a2, a3, b0, b1);
        }
    }

    int gr0 = rowBase + r0;
    int gr1 = gr0 + 8;
    if (gr0 < M) {
#pragma unroll
        for (int nt = 0; nt < NT; nt++)
            *reinterpret_cast<float2*>(C + (size_t)gr0 * NOUT + wc * NW + nt * 8 + c0 * 2) =
                make_float2(acc[nt][0], acc[nt][1]);
    }
    if (gr1 < M) {
#pragma unroll
        for (int nt = 0; nt < NT; nt++)
            *reinterpret_cast<float2*>(C + (size_t)gr1 * NOUT + wc * NW + nt * 8 + c0 * 2) =
                make_float2(acc[nt][2], acc[nt][3]);
    }
}

// ---------------- pull aggregation (8-edge unroll, 4 accumulator sets) --------
template <int FEAT, bool STATS>
__global__ void k_agg(const int* __restrict__ rowptr, const int2* __restrict__ csr,
                      const float* __restrict__ h2, const float* __restrict__ bias,
                      const float* __restrict__ normself, float* __restrict__ out,
                      float* stats, int n) {
    constexpr int LPN = FEAT / 4;     // lanes per node
    constexpr int NPW = 32 / LPN;     // nodes per warp
    const int lane = threadIdx.x & 31;
    const int warpG = (blockIdx.x * blockDim.x + threadIdx.x) >> 5;
    const int nWarps = (gridDim.x * blockDim.x) >> 5;
    const int sub = lane / LPN;
    const int fc = lane % LPN;

    pdl_trigger();
    pdl_wait();

    float4 bb = *reinterpret_cast<const float4*>(bias + fc * 4);

    float s0 = 0.f, s1 = 0.f, s2 = 0.f, s3 = 0.f;
    float q0 = 0.f, q1 = 0.f, q2 = 0.f, q3 = 0.f;

    for (int node = warpG * NPW + sub; node < n; node += nWarps * NPW) {
        int beg = rowptr[node];
        int end = rowptr[node + 1];
        float ns = normself[node];
        float4 h = *reinterpret_cast<const float4*>(h2 + (size_t)node * FEAT + fc * 4);
        float4 aA = make_float4(fmaf(ns, h.x, bb.x), fmaf(ns, h.y, bb.y),
                                fmaf(ns, h.z, bb.z), fmaf(ns, h.w, bb.w));
        float4 aB = make_float4(0.f, 0.f, 0.f, 0.f);
        float4 aC = make_float4(0.f, 0.f, 0.f, 0.f);
        float4 aD = make_float4(0.f, 0.f, 0.f, 0.f);
        int e = beg;
        for (; e + 7 < end; e += 8) {
            int2 m0 = csr[e],     m1 = csr[e + 1], m2 = csr[e + 2], m3 = csr[e + 3];
            int2 m4 = csr[e + 4], m5 = csr[e + 5], m6 = csr[e + 6], m7 = csr[e + 7];
            float4 v0 = *reinterpret_cast<const float4*>(h2 + (size_t)m0.x * FEAT + fc * 4);
            float4 v1 = *reinterpret_cast<const float4*>(h2 + (size_t)m1.x * FEAT + fc * 4);
            float4 v2 = *reinterpret_cast<const float4*>(h2 + (size_t)m2.x * FEAT + fc * 4);
            float4 v3 = *reinterpret_cast<const float4*>(h2 + (size_t)m3.x * FEAT + fc * 4);
            float4 v4 = *reinterpret_cast<const float4*>(h2 + (size_t)m4.x * FEAT + fc * 4);
            float4 v5 = *reinterpret_cast<const float4*>(h2 + (size_t)m5.x * FEAT + fc * 4);
            float4 v6 = *reinterpret_cast<const float4*>(h2 + (size_t)m6.x * FEAT + fc * 4);
            float4 v7 = *reinterpret_cast<const float4*>(h2 + (size_t)m7.x * FEAT + fc * 4);
            float n0 = __int_as_float(m0.y), n1 = __int_as_float(m1.y);
            float n2 = __int_as_float(m2.y), n3 = __int_as_float(m3.y);
            float n4 = __int_as_float(m4.y), n5 = __int_as_float(m5.y);
            float n6 = __int_as_float(m6.y), n7 = __int_as_float(m7.y);
            aA.x = fmaf(n0, v0.x, aA.x); aB.x = fmaf(n1, v1.x, aB.x);
            aC.x = fmaf(n2, v2.x, aC.x); aD.x = fmaf(n3, v3.x, aD.x);
            aA.y = fmaf(n0, v0.y, aA.y); aB.y = fmaf(n1, v1.y, aB.y);
            aC.y = fmaf(n2, v2.y, aC.y); aD.y = fmaf(n3, v3.y, aD.y);
            aA.z = fmaf(n0, v0.z, aA.z); aB.z = fmaf(n1, v1.z, aB.z);
            aC.z = fmaf(n2, v2.z, aC.z); aD.z = fmaf(n3, v3.z, aD.z);
            aA.w = fmaf(n0, v0.w, aA.w); aB.w = fmaf(n1, v1.w, aB.w);
            aC.w = fmaf(n2, v2.w, aC.w); aD.w = fmaf(n3, v3.w, aD.w);
            aA.x = fmaf(n4, v4.x, aA.x); aB.x = fmaf(n5, v5.x, aB.x);
            aC.x = fmaf(n6, v6.x, aC.x); aD.x = fmaf(n7, v7.x, aD.x);
            aA.y = fmaf(n4, v4.y, aA.y); aB.y = fmaf(n5, v5.y, aB.y);
            aC.y = fmaf(n6, v6.y, aC.y); aD.y = fmaf(n7, v7.y, aD.y);
            aA.z = fmaf(n4, v4.z, aA.z); aB.z = fmaf(n5, v5.z, aB.z);
            aC.z = fmaf(n6, v6.z, aC.z); aD.z = fmaf(n7, v7.z, aD.z);
            aA.w = fmaf(n4, v4.w, aA.w); aB.w = fmaf(n5, v5.w, aB.w);
            aC.w = fmaf(n6, v6.w, aC.w); aD.w = fmaf(n7, v7.w, aD.w);
        }
        for (; e + 1 < end; e += 2) {
            int2 m0 = csr[e], m1 = csr[e + 1];
            float4 v0 = *reinterpret_cast<const float4*>(h2 + (size_t)m0.x * FEAT + fc * 4);
            float4 v1 = *reinterpret_cast<const float4*>(h2 + (size_t)m1.x * FEAT + fc * 4);
            float n0 = __int_as_float(m0.y), n1 = __int_as_float(m1.y);
            aA.x = fmaf(n0, v0.x, aA.x); aB.x = fmaf(n1, v1.x, aB.x);
            aA.y = fmaf(n0, v0.y, aA.y); aB.y = fmaf(n1, v1.y, aB.y);
            aA.z = fmaf(n0, v0.z, aA.z); aB.z = fmaf(n1, v1.z, aB.z);
            aA.w = fmaf(n0, v0.w, aA.w); aB.w = fmaf(n1, v1.w, aB.w);
        }
        if (e < end) {
            int2 m0 = csr[e];
            float4 v0 = *reinterpret_cast<const float4*>(h2 + (size_t)m0.x * FEAT + fc * 4);
            float n0 = __int_as_float(m0.y);
            aA.x = fmaf(n0, v0.x, aA.x);
            aA.y = fmaf(n0, v0.y, aA.y);
            aA.z = fmaf(n0, v0.z, aA.z);
            aA.w = fmaf(n0, v0.w, aA.w);
        }
        float4 acc = make_float4((aA.x + aB.x) + (aC.x + aD.x),
                                 (aA.y + aB.y) + (aC.y + aD.y),
                                 (aA.z + aB.z) + (aC.z + aD.z),
                                 (aA.w + aB.w) + (aC.w + aD.w));
        *reinterpret_cast<float4*>(out + (size_t)node * FEAT + fc * 4) = acc;
        if (STATS) {
            s0 += acc.x; s1 += acc.y; s2 += acc.z; s3 += acc.w;
            q0 = fmaf(acc.x, acc.x, q0); q1 = fmaf(acc.y, acc.y, q1);
            q2 = fmaf(acc.z, acc.z, q2); q3 = fmaf(acc.w, acc.w, q3);
        }
    }

    if (STATS) {
#pragma unroll
        for (int off = 16; off >= LPN; off >>= 1) {
            s0 += __shfl_down_sync(0xffffffffu, s0, off);
            s1 += __shfl_down_sync(0xffffffffu, s1, off);
            s2 += __shfl_down_sync(0xffffffffu, s2, off);
            s3 += __shfl_down_sync(0xffffffffu, s3, off);
            q0 += __shfl_down_sync(0xffffffffu, q0, off);
            q1 += __shfl_down_sync(0xffffffffu, q1, off);
            q2 += __shfl_down_sync(0xffffffffu, q2, off);
            q3 += __shfl_down_sync(0xffffffffu, q3, off);
        }
        __shared__ float sh_s[8][FEAT];
        __shared__ float sh_q[8][FEAT];
        const int wid = threadIdx.x >> 5;
        if (lane < LPN) {
            sh_s[wid][fc * 4 + 0] = s0; sh_s[wid][fc * 4 + 1] = s1;
            sh_s[wid][fc * 4 + 2] = s2; sh_s[wid][fc * 4 + 3] = s3;
            sh_q[wid][fc * 4 + 0] = q0; sh_q[wid][fc * 4 + 1] = q1;
            sh_q[wid][fc * 4 + 2] = q2; sh_q[wid][fc * 4 + 3] = q3;
        }
        __syncthreads();
        int tid = threadIdx.x;
        if (tid < FEAT) {
            float a = 0.f, b = 0.f;
#pragma unroll
            for (int w = 0; w < 8; w++) { a += sh_s[w][tid]; b += sh_q[w][tid]; }
            atomicAdd(&stats[tid], a);
            atomicAdd(&stats[FEAT + tid], b);
        }
    }
}

// ---------------- host orchestration -----------------------------------------
static inline int cdiv(int a, int b) { return (a + b - 1) / b; }

extern "C" void kernel_launch(void* const* d_in, const int* in_sizes, int n_in,
                              void* d_out, int out_size) {
    const float* x      = (const float*)d_in[0];
    const int*   src    = (const int*)d_in[1];
    const int*   dst    = (const int*)d_in[2];
    const float* weight = (const float*)d_in[3];
    const float* W1 = (const float*)d_in[4];
    const float* b1 = (const float*)d_in[5];
    const float* ga1 = (const float*)d_in[6];
    const float* be1 = (const float*)d_in[7];
    const float* W2 = (const float*)d_in[8];
    const float* b2 = (const float*)d_in[9];
    const float* ga2 = (const float*)d_in[10];
    const float* be2 = (const float*)d_in[11];
    const float* W3 = (const float*)d_in[12];
    const float* b3 = (const float*)d_in[13];

    const int N = in_sizes[0] / 128;
    const int E = in_sizes[1];
    float* outp = (float*)d_out;

    void *p_deg, *p_cnt, *p_fill, *p_rowptr, *p_csr, *p_dinv, *p_ns, *p_h2, *p_out;
    void *p_state, *p_stats;
    cudaGetSymbolAddress(&p_deg, g_deg);
    cudaGetSymbolAddress(&p_cnt, g_cnt);
    cudaGetSymbolAddress(&p_fill, g_fill);
    cudaGetSymbolAddress(&p_rowptr, g_rowptr);
    cudaGetSymbolAddress(&p_csr, g_csr);
    cudaGetSymbolAddress(&p_dinv, g_dinv);
    cudaGetSymbolAddress(&p_ns, g_normself);
    cudaGetSymbolAddress(&p_h2, g_h2);
    cudaGetSymbolAddress(&p_out, g_out);
    cudaGetSymbolAddress(&p_state, g_scanstate);
    cudaGetSymbolAddress(&p_stats, g_stats);
    float* deg = (float*)p_deg;
    int* cnt = (int*)p_cnt;
    int* fill = (int*)p_fill;
    int* rowptr = (int*)p_rowptr;
    int2* csr = (int2*)p_csr;
    float* dinv = (float*)p_dinv;
    float* normself = (float*)p_ns;
    float* h2 = (float*)p_h2;
    float* agg = (float*)p_out;
    unsigned long long* scanstate = (unsigned long long*)p_state;
    float* stats1 = (float*)p_stats;        // layer1: 256 floats
    float* stats2 = (float*)p_stats + 256;  // layer2: 128 floats

    const float invN = 1.0f / (float)N;

    const int smem1 = (128 * (128 + 4) + 128 * (128 + 8)) * 4;
    const int smem2 = (128 * (128 + 4) + 128 * (64 + 8)) * 4;
    const int smem3 = (128 * (64 + 4) + 64 * (32 + 8)) * 4;
    cudaFuncSetAttribute(k_gemm_tc<128, 128, false>,
                         cudaFuncAttributeMaxDynamicSharedMemorySize, smem1);
    cudaFuncSetAttribute(k_gemm_tc<128, 64, true>,
                         cudaFuncAttributeMaxDynamicSharedMemorySize, smem2);
    cudaFuncSetAttribute(k_gemm_tc<64, 32, true>,
                         cudaFuncAttributeMaxDynamicSharedMemorySize, smem3);

    // side stream + fork/join events (host-side objects only)
    cudaStream_t s2;
    cudaEvent_t evFork, evJoin;
    cudaStreamCreateWithFlags(&s2, cudaStreamNonBlocking);
    cudaEventCreateWithFlags(&evFork, cudaEventDisableTiming);
    cudaEventCreateWithFlags(&evJoin, cudaEventDisableTiming);

    const int scanGrid = cdiv(N, 2048);   // 25 blocks for N=50000
    const int gemmGrid = cdiv(N, 128);
    const int aggGrid = 1184;             // 8 blocks/SM

    // PDL launch attribute (shared)
    cudaLaunchAttribute pdlAttr[1];
    pdlAttr[0].id = cudaLaunchAttributeProgrammaticStreamSerialization;
    pdlAttr[0].val.programmaticStreamSerializationAllowed = 1;

    // ---- fork: CSR/normalization prep on s2 (PDL-chained), concurrent with GEMM1 ----
    cudaEventRecord(evFork, 0);
    cudaStreamWaitEvent(s2, evFork, 0);

    k_init<<<cdiv(N, 256), 256, 0, s2>>>(deg, cnt, stats1, scanstate, N);
    {
        cudaLaunchConfig_t cfg{};
        cfg.gridDim = dim3(cdiv(E, 256), 1, 1);
        cfg.blockDim = dim3(256, 1, 1);
        cfg.stream = s2;
        cfg.attrs = pdlAttr; cfg.numAttrs = 1;
        cudaLaunchKernelEx(&cfg, k_prep_edge, dst, weight, deg, cnt, E);
    }
    {
        cudaLaunchConfig_t cfg{};
        cfg.gridDim = dim3(scanGrid, 1, 1);
        cfg.blockDim = dim3(256, 1, 1);
        cfg.stream = s2;
        cfg.attrs = pdlAttr; cfg.numAttrs = 1;
        cudaLaunchKernelEx(&cfg, k_scan, (const int*)cnt, (const float*)deg,
                           dinv, normself, rowptr, fill,
                           (volatile unsigned long long*)scanstate, N, E);
    }
    {
        cudaLaunchConfig_t cfg{};
        cfg.gridDim = dim3(cdiv(E, 256), 1, 1);
        cfg.blockDim = dim3(256, 1, 1);
        cfg.stream = s2;
        cfg.attrs = pdlAttr; cfg.numAttrs = 1;
        cudaLaunchKernelEx(&cfg, k_place, src, dst, weight, (const float*)dinv,
                           fill, csr, E);
    }
    cudaEventRecord(evJoin, s2);

    // Layer-1 GEMM on main stream (512 threads; independent of prep)
    k_gemm_tc<128, 128, false><<<gemmGrid, 512, smem1>>>(x, W1, h2, N,
                                                         nullptr, nullptr, nullptr, invN);

    // ---- join: everything after needs both GEMM1 and the CSR ----
    cudaStreamWaitEvent(0, evJoin, 0);

    // agg1: plain launch (predecessor is an event-wait, not a kernel)
    k_agg<128, true><<<aggGrid, 256>>>(rowptr, csr, h2, b1, normself, agg, stats1, N);

    {
        cudaLaunchConfig_t cfg{};
        cfg.gridDim = dim3(gemmGrid, 1, 1);
        cfg.blockDim = dim3(512, 1, 1);
        cfg.dynamicSmemBytes = smem2;
        cfg.stream = 0;
        cfg.attrs = pdlAttr;
        cfg.numAttrs = 1;
        cudaLaunchKernelEx(&cfg, k_gemm_tc<128, 64, true>, (const float*)agg, W2, h2, N,
                           ga1, be1, (const float*)stats1, invN);
    }
    {
        cudaLaunchConfig_t cfg{};
        cfg.gridDim = dim3(aggGrid, 1, 1);
        cfg.blockDim = dim3(256, 1, 1);
        cfg.dynamicSmemBytes = 0;
        cfg.stream = 0;
        cfg.attrs = pdlAttr;
        cfg.numAttrs = 1;
        cudaLaunchKernelEx(&cfg, k_agg<64, true>, (const int*)rowptr, (const int2*)csr,
                           (const float*)h2, b2, (const float*)normself, agg, stats2, N);
    }
    {
        cudaLaunchConfig_t cfg{};
        cfg.gridDim = dim3(gemmGrid, 1, 1);
        cfg.blockDim = dim3(512, 1, 1);
        cfg.dynamicSmemBytes = smem3;
        cfg.stream = 0;
        cfg.attrs = pdlAttr;
        cfg.numAttrs = 1;
        cudaLaunchKernelEx(&cfg, k_gemm_tc<64, 32, true>, (const float*)agg, W3, h2, N,
                           ga2, be2, (const float*)stats2, invN);
    }
    {
        cudaLaunchConfig_t cfg{};
        cfg.gridDim = dim3(aggGrid, 1, 1);
        cfg.blockDim = dim3(256, 1, 1);
        cfg.dynamicSmemBytes = 0;
        cfg.stream = 0;
        cfg.attrs = pdlAttr;
        cfg.numAttrs = 1;
        cudaLaunchKernelEx(&cfg, k_agg<32, false>, (const int*)rowptr, (const int2*)csr,
                           (const float*)h2, b3, (const float*)normself, outp,
                           (float*)nullptr, N);
    }
}

// round 17
// speedup vs baseline: 1.3651x; 1.0256x over previous
#include <cuda_runtime.h>
#include <cuda_bf16.h>
#include <cstdint>

#define EPS 1e-5f

static constexpr int MAX_N = 50048;    // nodes (actual 50000)
static constexpr int MAX_E = 600064;   // edges (actual 600000)

// ---------------- scratch (device globals; zero at load; zero-after-use) ------
__device__ float  g_wsum[MAX_N];       // edge-weight sums (zeroed by k_place)
__device__ int    g_cnt[MAX_N];        // in-degree counts (zeroed by k_place)
__device__ int    g_fill[MAX_N];
__device__ int    g_rowptr[MAX_N + 1];
__device__ int2   g_csr[MAX_E];        // (src, w*dinv[src] bits)
__device__ float  g_dinv[MAX_N];
__device__ float4 g_h2[MAX_N * 32];    // GEMM output (raw, up to 128 f/node)
__device__ float4 g_out[MAX_N * 32];   // aggregation output
__device__ float  g_stats[384];        // L1: [0:256) ; L2: [256:384) (zeroed by agg2/agg3)
__device__ unsigned long long g_scanstate[64];  // zeroed by k_place

// ---------------- PDL helpers --------------------------------------------------
__device__ __forceinline__ void pdl_wait() {
    asm volatile("griddepcontrol.wait;" ::: "memory");
}
__device__ __forceinline__ void pdl_trigger() {
    asm volatile("griddepcontrol.launch_dependents;" ::: "memory");
}

// ---------------- prep kernels -------------------------------------------------
// histogram into zero-initialized wsum/cnt (no init kernel needed)
__global__ void k_prep_edge(const int* __restrict__ dst, const float* __restrict__ w,
                            float* wsum, int* cnt, int e) {
    int i = blockIdx.x * blockDim.x + threadIdx.x;
    if (i < e) {
        int d = dst[i];
        atomicAdd(wsum + d, w[i]);
        atomicAdd(cnt + d, 1);
    }
}

// ---- fused single-pass scan (decoupled lookback) + dinv (deg = 1 + wsum) -----
__global__ void k_scan(const int* __restrict__ cnt, const float* __restrict__ wsum,
                       float* dinv, int* rowptr, int* fill,
                       volatile unsigned long long* state, int n, int e) {
    pdl_wait();   // prep_edge complete
    __shared__ int warpTot[8];
    __shared__ int blockOffSh;
    const int tid = threadIdx.x;
    const int lane = tid & 31;
    const int wid = tid >> 5;
    int tbase = blockIdx.x * 2048 + tid * 8;
    int v[8];
    int s = 0;
#pragma unroll
    for (int i = 0; i < 8; i++) {
        int idx = tbase + i;
        v[i] = (idx < n) ? cnt[idx] : 0;
        s += v[i];
        if (idx < n) {
            float d = 1.0f + wsum[idx];   // self loop weight 1
            dinv[idx] = rsqrtf(d);        // d >= 1 always
        }
    }
    int inc = s;
#pragma unroll
    for (int o = 1; o < 32; o <<= 1) {
        int t = __shfl_up_sync(0xffffffffu, inc, o);
        if (lane >= o) inc += t;
    }
    if (lane == 31) warpTot[wid] = inc;
    __syncthreads();
    if (wid == 0) {
        int wv = (lane < 8) ? warpTot[lane] : 0;
        int winc = wv;
#pragma unroll
        for (int o = 1; o < 8; o <<= 1) {
            int t = __shfl_up_sync(0xffffffffu, winc, o);
            if (lane >= o) winc += t;
        }
        if (lane < 8) warpTot[lane] = winc - wv;   // exclusive warp offsets
        int blockTotal = __shfl_sync(0xffffffffu, winc, 7);
        if (lane == 0) {
            if (blockIdx.x == 0) {
                __threadfence();
                state[0] = ((unsigned long long)blockTotal << 2) | 2ull;  // prefix
                blockOffSh = 0;
                rowptr[n] = e;
            } else {
                __threadfence();
                state[blockIdx.x] = ((unsigned long long)blockTotal << 2) | 1ull;  // aggregate
                int excl = 0;
                int j = blockIdx.x - 1;
                while (true) {
                    unsigned long long vv;
                    do { vv = state[j]; } while ((vv & 3ull) == 0ull);
                    excl += (int)(vv >> 2);
                    if ((vv & 3ull) == 2ull) break;
                    j--;
                }
                __threadfence();
                state[blockIdx.x] = ((unsigned long long)(excl + blockTotal) << 2) | 2ull;
                blockOffSh = excl;
            }
        }
    }
    __syncthreads();
    int run = blockOffSh + warpTot[wid] + (inc - s);
#pragma unroll
    for (int i = 0; i < 8; i++) {
        int idx = tbase + i;
        if (idx < n) {
            rowptr[idx] = run;
            fill[idx] = run;
            run += v[i];
        }
    }
}

// place: csr stores (src, w*dinv[src]) — ONE random gather per edge.
// Also resets wsum/cnt/scanstate for the next graph replay (zero-after-use).
__global__ void k_place(const int* __restrict__ src, const int* __restrict__ dst,
                        const float* __restrict__ w, const float* __restrict__ dinv,
                        int* fill, int2* csr,
                        float* wsum, int* cnt, unsigned long long* state,
                        int n, int e) {
    pdl_wait();   // scan complete (fill/dinv ready; wsum/cnt/state consumed)
    int i = blockIdx.x * blockDim.x + threadIdx.x;
    if (i < n) { wsum[i] = 0.0f; cnt[i] = 0; }
    if (i < 64) state[i] = 0ull;
    if (i < e) {
        int s = src[i], d = dst[i];
        float wt = w[i] * dinv[s];
        int pos = atomicAdd(fill + d, 1);
        csr[pos] = make_int2(s, __float_as_int(wt));
    }
}

// ---------------- tf32 helpers ------------------------------------------------
__device__ __forceinline__ uint32_t f2tf32(float f) {
    uint32_t r;
    asm("cvt.rna.tf32.f32 %0, %1;" : "=r"(r) : "f"(f));
    return r;
}

__device__ __forceinline__ void mma_tf32(float c[4], uint32_t a0, uint32_t a1,
                                         uint32_t a2, uint32_t a3,
                                         uint32_t b0, uint32_t b1) {
    asm volatile(
        "mma.sync.aligned.m16n8k8.row.col.f32.tf32.tf32.f32 "
        "{%0,%1,%2,%3}, {%4,%5,%6,%7}, {%8,%9}, {%0,%1,%2,%3};"
        : "+f"(c[0]), "+f"(c[1]), "+f"(c[2]), "+f"(c[3])
        : "r"(a0), "r"(a1), "r"(a2), "r"(a3), "r"(b0), "r"(b1));
}

// ---------------- tf32 GEMM: BM=128 whole-K, 512 threads, 8x2 warp grid -------
// Pre-wait B staging (overlaps predecessor agg); 16 resident warps/SM.
template <int K, int NOUT, bool BN>
__global__ void k_gemm_tc(const float* __restrict__ A, const float* __restrict__ B,
                          float* __restrict__ C, int M,
                          const float* __restrict__ gamma, const float* __restrict__ beta,
                          const float* __restrict__ stats, float invN) {
    constexpr int BM = 128;
    constexpr int SA = K + 4;
    constexpr int SB = NOUT + 8;
    constexpr int NW = NOUT / 2;     // columns per warp-column group
    constexpr int NT = NW / 8;       // n8-tiles per warp (8/4/2)

    extern __shared__ uint32_t sm[];
    uint32_t* As = sm;               // [BM][SA]
    uint32_t* Bs = sm + BM * SA;     // [K][SB]
    __shared__ float sscale[K];
    __shared__ float sshift[K];

    const int tid = threadIdx.x;     // 512 threads
    const int lane = tid & 31;
    const int warp = tid >> 5;       // 0..15
    const int wr = warp & 7;         // warp row 0..7 (16 rows each)
    const int wc = warp >> 3;        // warp col 0..1 (NW cols each)
    const int rowBase = blockIdx.x * BM;

    // --- pre-wait prologue: stage B (weights are harness inputs) ---
    for (int l = tid; l < K * NOUT / 4; l += 512) {
        int r = l / (NOUT / 4);
        int c4 = l % (NOUT / 4);
        float4 v = *reinterpret_cast<const float4*>(B + (size_t)r * NOUT + c4 * 4);
        uint32_t* p = Bs + r * SB + c4 * 4;
        p[0] = f2tf32(v.x); p[1] = f2tf32(v.y); p[2] = f2tf32(v.z); p[3] = f2tf32(v.w);
    }

    pdl_wait();   // predecessor (agg) output now visible

    if (BN && tid < K) {
        float s = stats[tid];
        float q = stats[K + tid];
        float mean = s * invN;
        float var = q * invN - mean * mean;
        float sc = gamma[tid] * rsqrtf(var + EPS);
        sscale[tid] = sc;
        sshift[tid] = beta[tid] - mean * sc;
    }
    if (BN) __syncthreads();   // sscale/sshift visible before A staging

    for (int l = tid; l < BM * K / 4; l += 512) {
        int r = l / (K / 4);
        int c4 = l % (K / 4);
        int gr = rowBase + r;
        float4 v = make_float4(0.f, 0.f, 0.f, 0.f);
        if (gr < M) v = *reinterpret_cast<const float4*>(A + (size_t)gr * K + c4 * 4);
        if (BN) {
            v.x = fmaxf(fmaf(v.x, sscale[c4 * 4 + 0], sshift[c4 * 4 + 0]), 0.f);
            v.y = fmaxf(fmaf(v.y, sscale[c4 * 4 + 1], sshift[c4 * 4 + 1]), 0.f);
            v.z = fmaxf(fmaf(v.z, sscale[c4 * 4 + 2], sshift[c4 * 4 + 2]), 0.f);
            v.w = fmaxf(fmaf(v.w, sscale[c4 * 4 + 3], sshift[c4 * 4 + 3]), 0.f);
        }
        uint32_t* p = As + r * SA + c4 * 4;
        p[0] = f2tf32(v.x); p[1] = f2tf32(v.y); p[2] = f2tf32(v.z); p[3] = f2tf32(v.w);
    }
    __syncthreads();
    pdl_trigger();   // all global reads of A (and stats) done; dependents may launch

    float acc[NT][4];
#pragma unroll
    for (int nt = 0; nt < NT; nt++) {
        acc[nt][0] = 0.f; acc[nt][1] = 0.f; acc[nt][2] = 0.f; acc[nt][3] = 0.f;
    }

    const int r0 = (wr << 4) + (lane >> 2);   // 0..127
    const int c0 = lane & 3;
    const int bcol = lane >> 2;

#pragma unroll 4
    for (int kk = 0; kk < K; kk += 8) {
        uint32_t a0 = As[r0 * SA + kk + c0];
        uint32_t a1 = As[(r0 + 8) * SA + kk + c0];
        uint32_t a2 = As[r0 * SA + kk + c0 + 4];
        uint32_t a3 = As[(r0 + 8) * SA + kk + c0 + 4];
#pragma unroll
        for (int nt = 0; nt < NT; nt++) {
            uint32_t b0 = Bs[(kk + c0) * SB + wc * NW + nt * 8 + bcol];
            uint32_t b1 = Bs[(kk + c0 + 4) * SB + wc * NW + nt * 8 + bcol];
            mma_tf32(acc[nt], a0, a1, a2, a3, b0, b1);
        }
    }

    int gr0 = rowBase + r0;
    int gr1 = gr0 + 8;
    if (gr0 < M) {
#pragma unroll
        for (int nt = 0; nt < NT; nt++)
            *reinterpret_cast<float2*>(C + (size_t)gr0 * NOUT + wc * NW + nt * 8 + c0 * 2) =
                make_float2(acc[nt][0], acc[nt][1]);
    }
    if (gr1 < M) {
#pragma unroll
        for (int nt = 0; nt < NT; nt++)
            *reinterpret_cast<float2*>(C + (size_t)gr1 * NOUT + wc * NW + nt * 8 + c0 * 2) =
                make_float2(acc[nt][2], acc[nt][3]);
    }
}

// ---------------- pull aggregation (8-edge unroll, 4 accumulator sets) --------
// csr weight is w*dinv[src]; out = dinv[d]*edgeSum + dinv[d]^2*h2[d] + b.
// zeroStats: previous layer's stats buffer, reset for next replay (PDL-safe:
// all predecessor gemm blocks read it before triggering).
template <int FEAT, bool STATS>
__global__ void k_agg(const int* __restrict__ rowptr, const int2* __restrict__ csr,
                      const float* __restrict__ h2, const float* __restrict__ bias,
                      const float* __restrict__ dinv, float* __restrict__ out,
                      float* stats, float* zeroStats, int zeroCount, int n) {
    constexpr int LPN = FEAT / 4;     // lanes per node
    constexpr int NPW = 32 / LPN;     // nodes per warp
    const int lane = threadIdx.x & 31;
    const int warpG = (blockIdx.x * blockDim.x + threadIdx.x) >> 5;
    const int nWarps = (gridDim.x * blockDim.x) >> 5;
    const int sub = lane / LPN;
    const int fc = lane % LPN;

    pdl_trigger();
    pdl_wait();

    if (zeroCount > 0 && blockIdx.x == 0 && threadIdx.x < zeroCount)
        zeroStats[threadIdx.x] = 0.0f;

    float4 bb = *reinterpret_cast<const float4*>(bias + fc * 4);

    float s0 = 0.f, s1 = 0.f, s2 = 0.f, s3 = 0.f;
    float q0 = 0.f, q1 = 0.f, q2 = 0.f, q3 = 0.f;

    for (int node = warpG * NPW + sub; node < n; node += nWarps * NPW) {
        int beg = rowptr[node];
        int end = rowptr[node + 1];
        float dn = dinv[node];
        float4 h = *reinterpret_cast<const float4*>(h2 + (size_t)node * FEAT + fc * 4);
        float4 aA = make_float4(0.f, 0.f, 0.f, 0.f);
        float4 aB = make_float4(0.f, 0.f, 0.f, 0.f);
        float4 aC = make_float4(0.f, 0.f, 0.f, 0.f);
        float4 aD = make_float4(0.f, 0.f, 0.f, 0.f);
        int e = beg;
        for (; e + 7 < end; e += 8) {
            int2 m0 = csr[e],     m1 = csr[e + 1], m2 = csr[e + 2], m3 = csr[e + 3];
            int2 m4 = csr[e + 4], m5 = csr[e + 5], m6 = csr[e + 6], m7 = csr[e + 7];
            float4 v0 = *reinterpret_cast<const float4*>(h2 + (size_t)m0.x * FEAT + fc * 4);
            float4 v1 = *reinterpret_cast<const float4*>(h2 + (size_t)m1.x * FEAT + fc * 4);
            float4 v2 = *reinterpret_cast<const float4*>(h2 + (size_t)m2.x * FEAT + fc * 4);
            float4 v3 = *reinterpret_cast<const float4*>(h2 + (size_t)m3.x * FEAT + fc * 4);
            float4 v4 = *reinterpret_cast<const float4*>(h2 + (size_t)m4.x * FEAT + fc * 4);
            float4 v5 = *reinterpret_cast<const float4*>(h2 + (size_t)m5.x * FEAT + fc * 4);
            float4 v6 = *reinterpret_cast<const float4*>(h2 + (size_t)m6.x * FEAT + fc * 4);
            float4 v7 = *reinterpret_cast<const float4*>(h2 + (size_t)m7.x * FEAT + fc * 4);
            float n0 = __int_as_float(m0.y), n1 = __int_as_float(m1.y);
            float n2 = __int_as_float(m2.y), n3 = __int_as_float(m3.y);
            float n4 = __int_as_float(m4.y), n5 = __int_as_float(m5.y);
            float n6 = __int_as_float(m6.y), n7 = __int_as_float(m7.y);
            aA.x = fmaf(n0, v0.x, aA.x); aB.x = fmaf(n1, v1.x, aB.x);
            aC.x = fmaf(n2, v2.x, aC.x); aD.x = fmaf(n3, v3.x, aD.x);
            aA.y = fmaf(n0, v0.y, aA.y); aB.y = fmaf(n1, v1.y, aB.y);
            aC.y = fmaf(n2, v2.y, aC.y); aD.y = fmaf(n3, v3.y, aD.y);
            aA.z = fmaf(n0, v0.z, aA.z); aB.z = fmaf(n1, v1.z, aB.z);
            aC.z = fmaf(n2, v2.z, aC.z); aD.z = fmaf(n3, v3.z, aD.z);
            aA.w = fmaf(n0, v0.w, aA.w); aB.w = fmaf(n1, v1.w, aB.w);
            aC.w = fmaf(n2, v2.w, aC.w); aD.w = fmaf(n3, v3.w, aD.w);
            aA.x = fmaf(n4, v4.x, aA.x); aB.x = fmaf(n5, v5.x, aB.x);
            aC.x = fmaf(n6, v6.x, aC.x); aD.x = fmaf(n7, v7.x, aD.x);
            aA.y = fmaf(n4, v4.y, aA.y); aB.y = fmaf(n5, v5.y, aB.y);
            aC.y = fmaf(n6, v6.y, aC.y); aD.y = fmaf(n7, v7.y, aD.y);
            aA.z = fmaf(n4, v4.z, aA.z); aB.z = fmaf(n5, v5.z, aB.z);
            aC.z = fmaf(n6, v6.z, aC.z); aD.z = fmaf(n7, v7.z, aD.z);
            aA.w = fmaf(n4, v4.w, aA.w); aB.w = fmaf(n5, v5.w, aB.w);
            aC.w = fmaf(n6, v6.w, aC.w); aD.w = fmaf(n7, v7.w, aD.w);
        }
        for (; e + 1 < end; e += 2) {
            int2 m0 = csr[e], m1 = csr[e + 1];
            float4 v0 = *reinterpret_cast<const float4*>(h2 + (size_t)m0.x * FEAT + fc * 4);
            float4 v1 = *reinterpret_cast<const float4*>(h2 + (size_t)m1.x * FEAT + fc * 4);
            float n0 = __int_as_float(m0.y), n1 = __int_as_float(m1.y);
            aA.x = fmaf(n0, v0.x, aA.x); aB.x = fmaf(n1, v1.x, aB.x);
            aA.y = fmaf(n0, v0.y, aA.y); aB.y = fmaf(n1, v1.y, aB.y);
            aA.z = fmaf(n0, v0.z, aA.z); aB.z = fmaf(n1, v1.z, aB.z);
            aA.w = fmaf(n0, v0.w, aA.w); aB.w = fmaf(n1, v1.w, aB.w);
        }
        if (e < end) {
            int2 m0 = csr[e];
            float4 v0 = *reinterpret_cast<const float4*>(h2 + (size_t)m0.x * FEAT + fc * 4);
            float n0 = __int_as_float(m0.y);
            aA.x = fmaf(n0, v0.x, aA.x);
            aA.y = fmaf(n0, v0.y, aA.y);
            aA.z = fmaf(n0, v0.z, aA.z);
            aA.w = fmaf(n0, v0.w, aA.w);
        }
        float es_x = (aA.x + aB.x) + (aC.x + aD.x);
        float es_y = (aA.y + aB.y) + (aC.y + aD.y);
        float es_z = (aA.z + aB.z) + (aC.z + aD.z);
        float es_w = (aA.w + aB.w) + (aC.w + aD.w);
        float dn2 = dn * dn;
        float4 acc;
        acc.x = fmaf(dn, es_x, fmaf(dn2, h.x, bb.x));
        acc.y = fmaf(dn, es_y, fmaf(dn2, h.y, bb.y));
        acc.z = fmaf(dn, es_z, fmaf(dn2, h.z, bb.z));
        acc.w = fmaf(dn, es_w, fmaf(dn2, h.w, bb.w));
        *reinterpret_cast<float4*>(out + (size_t)node * FEAT + fc * 4) = acc;
        if (STATS) {
            s0 += acc.x; s1 += acc.y; s2 += acc.z; s3 += acc.w;
            q0 = fmaf(acc.x, acc.x, q0); q1 = fmaf(acc.y, acc.y, q1);
            q2 = fmaf(acc.z, acc.z, q2); q3 = fmaf(acc.w, acc.w, q3);
        }
    }

    if (STATS) {
#pragma unroll
        for (int off = 16; off >= LPN; off >>= 1) {
            s0 += __shfl_down_sync(0xffffffffu, s0, off);
            s1 += __shfl_down_sync(0xffffffffu, s1, off);
            s2 += __shfl_down_sync(0xffffffffu, s2, off);
            s3 += __shfl_down_sync(0xffffffffu, s3, off);
            q0 += __shfl_down_sync(0xffffffffu, q0, off);
            q1 += __shfl_down_sync(0xffffffffu, q1, off);
            q2 += __shfl_down_sync(0xffffffffu, q2, off);
            q3 += __shfl_down_sync(0xffffffffu, q3, off);
        }
        __shared__ float sh_s[8][FEAT];
        __shared__ float sh_q[8][FEAT];
        const int wid = threadIdx.x >> 5;
        if (lane < LPN) {
            sh_s[wid][fc * 4 + 0] = s0; sh_s[wid][fc * 4 + 1] = s1;
            sh_s[wid][fc * 4 + 2] = s2; sh_s[wid][fc * 4 + 3] = s3;
            sh_q[wid][fc * 4 + 0] = q0; sh_q[wid][fc * 4 + 1] = q1;
            sh_q[wid][fc * 4 + 2] = q2; sh_q[wid][fc * 4 + 3] = q3;
        }
        __syncthreads();
        int tid = threadIdx.x;
        if (tid < FEAT) {
            float a = 0.f, b = 0.f;
#pragma unroll
            for (int w = 0; w < 8; w++) { a += sh_s[w][tid]; b += sh_q[w][tid]; }
            atomicAdd(&stats[tid], a);
            atomicAdd(&stats[FEAT + tid], b);
        }
    }
}

// ---------------- host orchestration -----------------------------------------
static inline int cdiv(int a, int b) { return (a + b - 1) / b; }

extern "C" void kernel_launch(void* const* d_in, const int* in_sizes, int n_in,
                              void* d_out, int out_size) {
    const float* x      = (const float*)d_in[0];
    const int*   src    = (const int*)d_in[1];
    const int*   dst    = (const int*)d_in[2];
    const float* weight = (const float*)d_in[3];
    const float* W1 = (const float*)d_in[4];
    const float* b1 = (const float*)d_in[5];
    const float* ga1 = (const float*)d_in[6];
    const float* be1 = (const float*)d_in[7];
    const float* W2 = (const float*)d_in[8];
    const float* b2 = (const float*)d_in[9];
    const float* ga2 = (const float*)d_in[10];
    const float* be2 = (const float*)d_in[11];
    const float* W3 = (const float*)d_in[12];
    const float* b3 = (const float*)d_in[13];

    const int N = in_sizes[0] / 128;
    const int E = in_sizes[1];
    float* outp = (float*)d_out;

    void *p_wsum, *p_cnt, *p_fill, *p_rowptr, *p_csr, *p_dinv, *p_h2, *p_out;
    void *p_state, *p_stats;
    cudaGetSymbolAddress(&p_wsum, g_wsum);
    cudaGetSymbolAddress(&p_cnt, g_cnt);
    cudaGetSymbolAddress(&p_fill, g_fill);
    cudaGetSymbolAddress(&p_rowptr, g_rowptr);
    cudaGetSymbolAddress(&p_csr, g_csr);
    cudaGetSymbolAddress(&p_dinv, g_dinv);
    cudaGetSymbolAddress(&p_h2, g_h2);
    cudaGetSymbolAddress(&p_out, g_out);
    cudaGetSymbolAddress(&p_state, g_scanstate);
    cudaGetSymbolAddress(&p_stats, g_stats);
    float* wsum = (float*)p_wsum;
    int* cnt = (int*)p_cnt;
    int* fill = (int*)p_fill;
    int* rowptr = (int*)p_rowptr;
    int2* csr = (int2*)p_csr;
    float* dinv = (float*)p_dinv;
    float* h2 = (float*)p_h2;
    float* agg = (float*)p_out;
    unsigned long long* scanstate = (unsigned long long*)p_state;
    float* stats1 = (float*)p_stats;        // layer1: 256 floats
    float* stats2 = (float*)p_stats + 256;  // layer2: 128 floats

    const float invN = 1.0f / (float)N;

    const int smem1 = (128 * (128 + 4) + 128 * (128 + 8)) * 4;
    const int smem2 = (128 * (128 + 4) + 128 * (64 + 8)) * 4;
    const int smem3 = (128 * (64 + 4) + 64 * (32 + 8)) * 4;
    cudaFuncSetAttribute(k_gemm_tc<128, 128, false>,
                         cudaFuncAttributeMaxDynamicSharedMemorySize, smem1);
    cudaFuncSetAttribute(k_gemm_tc<128, 64, true>,
                         cudaFuncAttributeMaxDynamicSharedMemorySize, smem2);
    cudaFuncSetAttribute(k_gemm_tc<64, 32, true>,
                         cudaFuncAttributeMaxDynamicSharedMemorySize, smem3);

    // side stream + fork/join events (host-side objects only)
    cudaStream_t s2;
    cudaEvent_t evFork, evJoin;
    cudaStreamCreateWithFlags(&s2, cudaStreamNonBlocking);
    cudaEventCreateWithFlags(&evFork, cudaEventDisableTiming);
    cudaEventCreateWithFlags(&evJoin, cudaEventDisableTiming);

    const int scanGrid = cdiv(N, 2048);   // 25 blocks for N=50000
    const int gemmGrid = cdiv(N, 128);
    const int aggGrid = 1184;             // 8 blocks/SM

    // PDL launch attribute (shared)
    cudaLaunchAttribute pdlAttr[1];
    pdlAttr[0].id = cudaLaunchAttributeProgrammaticStreamSerialization;
    pdlAttr[0].val.programmaticStreamSerializationAllowed = 1;

    // ---- fork: CSR prep on s2 (PDL-chained), concurrent with Layer-1 GEMM ----
    cudaEventRecord(evFork, 0);
    cudaStreamWaitEvent(s2, evFork, 0);

    k_prep_edge<<<cdiv(E, 256), 256, 0, s2>>>(dst, weight, wsum, cnt, E);
    {
        cudaLaunchConfig_t cfg{};
        cfg.gridDim = dim3(scanGrid, 1, 1);
        cfg.blockDim = dim3(256, 1, 1);
        cfg.stream = s2;
        cfg.attrs = pdlAttr; cfg.numAttrs = 1;
        cudaLaunchKernelEx(&cfg, k_scan, (const int*)cnt, (const float*)wsum,
                           dinv, rowptr, fill,
                           (volatile unsigned long long*)scanstate, N, E);
    }
    {
        cudaLaunchConfig_t cfg{};
        cfg.gridDim = dim3(cdiv(E, 256), 1, 1);
        cfg.blockDim = dim3(256, 1, 1);
        cfg.stream = s2;
        cfg.attrs = pdlAttr; cfg.numAttrs = 1;
        cudaLaunchKernelEx(&cfg, k_place, src, dst, weight, (const float*)dinv,
                           fill, csr, wsum, cnt, scanstate, N, E);
    }
    cudaEventRecord(evJoin, s2);

    // Layer-1 GEMM on main stream (512 threads; fully independent of prep)
    k_gemm_tc<128, 128, false><<<gemmGrid, 512, smem1>>>(x, W1, h2, N,
                                                         nullptr, nullptr, nullptr, invN);

    // ---- join: everything after needs both GEMM1 and the CSR ----
    cudaStreamWaitEvent(0, evJoin, 0);

    // agg1: plain launch (predecessor is an event-wait, not a kernel)
    k_agg<128, true><<<aggGrid, 256>>>(rowptr, csr, h2, b1, dinv, agg, stats1,
                                       (float*)nullptr, 0, N);

    {
        cudaLaunchConfig_t cfg{};
        cfg.gridDim = dim3(gemmGrid, 1, 1);
        cfg.blockDim = dim3(512, 1, 1);
        cfg.dynamicSmemBytes = smem2;
        cfg.stream = 0;
        cfg.attrs = pdlAttr;
        cfg.numAttrs = 1;
        cudaLaunchKernelEx(&cfg, k_gemm_tc<128, 64, true>, (const float*)agg, W2, h2, N,
                           ga1, be1, (const float*)stats1, invN);
    }
    {
        // agg2 zeroes stats1 (gemm2's every block has read it before triggering)
        cudaLaunchConfig_t cfg{};
        cfg.gridDim = dim3(aggGrid, 1, 1);
        cfg.blockDim = dim3(256, 1, 1);
        cfg.dynamicSmemBytes = 0;
        cfg.stream = 0;
        cfg.attrs = pdlAttr;
        cfg.numAttrs = 1;
        cudaLaunchKernelEx(&cfg, k_agg<64, true>, (const int*)rowptr, (const int2*)csr,
                           (const float*)h2, b2, (const float*)dinv, agg, stats2,
                           stats1, 256, N);
    }
    {
        cudaLaunchConfig_t cfg{};
        cfg.gridDim = dim3(gemmGrid, 1, 1);
        cfg.blockDim = dim3(512, 1, 1);
        cfg.dynamicSmemBytes = smem3;
        cfg.stream = 0;
        cfg.attrs = pdlAttr;
        cfg.numAttrs = 1;
        cudaLaunchKernelEx(&cfg, k_gemm_tc<64, 32, true>, (const float*)agg, W3, h2, N,
                           ga2, be2, (const float*)stats2, invN);
    }
    {
        // agg3 zeroes stats2
        cudaLaunchConfig_t cfg{};
        cfg.gridDim = dim3(aggGrid, 1, 1);
        cfg.blockDim = dim3(256, 1, 1);
        cfg.dynamicSmemBytes = 0;
        cfg.stream = 0;
        cfg.attrs = pdlAttr;
        cfg.numAttrs = 1;
        cudaLaunchKernelEx(&cfg, k_agg<32, false>, (const int*)rowptr, (const int2*)csr,
                           (const float*)h2, b3, (const float*)dinv, outp,
                           (float*)nullptr, stats2, 128, N);
    }
}